// round 1
// baseline (speedup 1.0000x reference)
#include <cuda_runtime.h>
#include <cuda_bf16.h>

#define HID   2048
#define HD    128
#define NH    16
#define BATCH 2
#define SEQ   2048
#define MROWS (BATCH*SEQ)   // 4096

// Scratch buffers (no allocation allowed -> __device__ globals)
__device__ float g_q[(size_t)MROWS * HID];   // [b*s, heads*hd]
__device__ float g_k[(size_t)MROWS * HD];    // [b*s, hd]
__device__ float g_v[(size_t)MROWS * HD];
__device__ float g_o[(size_t)MROWS * HID];

// ---------------------------------------------------------------------------
// GEMM: C[M,N] = A[M,K] * B[N,K]^T   (B row-major [N,K], i.e. nn.Linear weight)
// 128x128 block tile, BK=8, 256 threads, 8x8 per-thread register tile.
// M,N,K all divisible by tile dims for every call here.
// ---------------------------------------------------------------------------
__global__ __launch_bounds__(256) void gemm_abt(
    const float* __restrict__ A, const float* __restrict__ B,
    float* __restrict__ C, int M, int N, int K)
{
    __shared__ float As[8][128];
    __shared__ float Bs[8][128];

    const int tid = threadIdx.x;
    const int tx = tid & 15;        // 0..15 -> N direction
    const int ty = tid >> 4;        // 0..15 -> M direction
    const int m0 = blockIdx.y * 128;
    const int n0 = blockIdx.x * 128;

    float acc[8][8];
#pragma unroll
    for (int i = 0; i < 8; i++)
#pragma unroll
        for (int j = 0; j < 8; j++) acc[i][j] = 0.f;

    const int ldRow = tid >> 1;           // 0..127
    const int ldCol = (tid & 1) * 4;      // 0 or 4

    for (int kt = 0; kt < K; kt += 8) {
        float4 av = *(const float4*)&A[(size_t)(m0 + ldRow) * K + kt + ldCol];
        float4 bv = *(const float4*)&B[(size_t)(n0 + ldRow) * K + kt + ldCol];
        As[ldCol + 0][ldRow] = av.x; As[ldCol + 1][ldRow] = av.y;
        As[ldCol + 2][ldRow] = av.z; As[ldCol + 3][ldRow] = av.w;
        Bs[ldCol + 0][ldRow] = bv.x; Bs[ldCol + 1][ldRow] = bv.y;
        Bs[ldCol + 2][ldRow] = bv.z; Bs[ldCol + 3][ldRow] = bv.w;
        __syncthreads();

#pragma unroll
        for (int kk = 0; kk < 8; kk++) {
            float ra[8], rb[8];
#pragma unroll
            for (int i = 0; i < 8; i++) ra[i] = As[kk][ty * 8 + i];
#pragma unroll
            for (int j = 0; j < 8; j++) rb[j] = Bs[kk][tx * 8 + j];
#pragma unroll
            for (int i = 0; i < 8; i++)
#pragma unroll
                for (int j = 0; j < 8; j++) acc[i][j] += ra[i] * rb[j];
        }
        __syncthreads();
    }

#pragma unroll
    for (int i = 0; i < 8; i++) {
        float4* cp = (float4*)&C[(size_t)(m0 + ty * 8 + i) * N + n0 + tx * 8];
        cp[0] = make_float4(acc[i][0], acc[i][1], acc[i][2], acc[i][3]);
        cp[1] = make_float4(acc[i][4], acc[i][5], acc[i][6], acc[i][7]);
    }
}

// ---------------------------------------------------------------------------
// Flash-attention MQA.
// Block = (b, h, 64-query tile). 256 threads as 16(ty: rows) x 16(tx: cols).
// Each thread: 4 query rows (ty*4+i), S cols tx+16j (j<4), O cols tx+16j (j<8).
// K/V streamed in 64-key chunks via SMEM; online softmax; O in registers.
// ---------------------------------------------------------------------------
#define KPAD 129   // 128 + 1: column-strided reads (stride 129) hit distinct banks
#define PPAD 65

__global__ __launch_bounds__(256) void flash_mqa(
    const float* __restrict__ Q, const float* __restrict__ Kg,
    const float* __restrict__ Vg, float* __restrict__ O)
{
    extern __shared__ float sm[];
    float* Qs = sm;                    // 64 x KPAD
    float* Ks = Qs + 64 * KPAD;        // 64 x KPAD
    float* Vs = Ks + 64 * KPAD;        // 64 x KPAD
    float* Ps = Vs + 64 * KPAD;        // 64 x PPAD

    const int tid = threadIdx.x;
    const int tx = tid & 15;
    const int ty = tid >> 4;
    const int b  = blockIdx.x >> 4;
    const int h  = blockIdx.x & 15;
    const int q0 = blockIdx.y * 64;
    const float scale = 0.08838834764831845f;   // 1/sqrt(128)

    // Load Q tile [64 x 128]
    const float* qbase = Q + ((size_t)(b * SEQ + q0)) * HID + h * HD;
#pragma unroll
    for (int it = 0; it < 8; it++) {
        int idx4 = tid + it * 256;          // 0..2047 float4s
        int r  = idx4 >> 5;                 // 32 float4 per row
        int c4 = (idx4 & 31) * 4;
        float4 v = *(const float4*)&qbase[(size_t)r * HID + c4];
        Qs[r * KPAD + c4 + 0] = v.x; Qs[r * KPAD + c4 + 1] = v.y;
        Qs[r * KPAD + c4 + 2] = v.z; Qs[r * KPAD + c4 + 3] = v.w;
    }

    float m[4], l[4], acc[4][8];
#pragma unroll
    for (int i = 0; i < 4; i++) {
        m[i] = -1e30f; l[i] = 0.f;
#pragma unroll
        for (int j = 0; j < 8; j++) acc[i][j] = 0.f;
    }
    __syncthreads();

    const float* kbase = Kg + (size_t)b * SEQ * HD;
    const float* vbase = Vg + (size_t)b * SEQ * HD;

    for (int t0 = 0; t0 < SEQ; t0 += 64) {
        // Load K,V chunks [64 x 128]
#pragma unroll
        for (int it = 0; it < 8; it++) {
            int idx4 = tid + it * 256;
            int r  = idx4 >> 5;
            int c4 = (idx4 & 31) * 4;
            float4 kv = *(const float4*)&kbase[(size_t)(t0 + r) * HD + c4];
            float4 vv = *(const float4*)&vbase[(size_t)(t0 + r) * HD + c4];
            Ks[r * KPAD + c4 + 0] = kv.x; Ks[r * KPAD + c4 + 1] = kv.y;
            Ks[r * KPAD + c4 + 2] = kv.z; Ks[r * KPAD + c4 + 3] = kv.w;
            Vs[r * KPAD + c4 + 0] = vv.x; Vs[r * KPAD + c4 + 1] = vv.y;
            Vs[r * KPAD + c4 + 2] = vv.z; Vs[r * KPAD + c4 + 3] = vv.w;
        }
        __syncthreads();

        // S = Q * K^T (scaled): 4x4 per thread, rows ty*4+i, cols tx+16*j
        float s[4][4];
#pragma unroll
        for (int i = 0; i < 4; i++)
#pragma unroll
            for (int j = 0; j < 4; j++) s[i][j] = 0.f;

        for (int k = 0; k < HD; k++) {
            float rq[4], rk[4];
#pragma unroll
            for (int i = 0; i < 4; i++) rq[i] = Qs[(ty * 4 + i) * KPAD + k];
#pragma unroll
            for (int j = 0; j < 4; j++) rk[j] = Ks[(tx + 16 * j) * KPAD + k];
#pragma unroll
            for (int i = 0; i < 4; i++)
#pragma unroll
                for (int j = 0; j < 4; j++) s[i][j] += rq[i] * rk[j];
        }

        // Online softmax per row. Reduction across the 16 tx lanes (xor 1..8
        // stays inside each 16-lane half-warp; all 16 share the same ty/rows).
#pragma unroll
        for (int i = 0; i < 4; i++) {
            float mloc = fmaxf(fmaxf(s[i][0] * scale, s[i][1] * scale),
                               fmaxf(s[i][2] * scale, s[i][3] * scale));
#pragma unroll
            for (int o = 1; o < 16; o <<= 1)
                mloc = fmaxf(mloc, __shfl_xor_sync(0xffffffffu, mloc, o));
            float mn    = fmaxf(m[i], mloc);
            float alpha = __expf(m[i] - mn);
            float ps = 0.f;
#pragma unroll
            for (int j = 0; j < 4; j++) {
                float p = __expf(s[i][j] * scale - mn);
                s[i][j] = p;
                ps += p;
            }
#pragma unroll
            for (int o = 1; o < 16; o <<= 1)
                ps += __shfl_xor_sync(0xffffffffu, ps, o);
            l[i] = l[i] * alpha + ps;
            m[i] = mn;
#pragma unroll
            for (int j = 0; j < 8; j++) acc[i][j] *= alpha;
#pragma unroll
            for (int j = 0; j < 4; j++)
                Ps[(ty * 4 + i) * PPAD + tx + 16 * j] = s[i][j];
        }
        __syncthreads();

        // O += P * V : V cols tx+16*j are lane-consecutive -> conflict-free
        for (int t = 0; t < 64; t++) {
            float rv[8];
#pragma unroll
            for (int j = 0; j < 8; j++) rv[j] = Vs[t * KPAD + tx + 16 * j];
#pragma unroll
            for (int i = 0; i < 4; i++) {
                float p = Ps[(ty * 4 + i) * PPAD + t];
#pragma unroll
                for (int j = 0; j < 8; j++) acc[i][j] += p * rv[j];
            }
        }
        __syncthreads();
    }

    // Epilogue: O[b, q0+r, h*128 + c] = acc / l
    float* obase = O + ((size_t)(b * SEQ + q0)) * HID + h * HD;
#pragma unroll
    for (int i = 0; i < 4; i++) {
        float inv = 1.f / l[i];
#pragma unroll
        for (int j = 0; j < 8; j++)
            obase[(size_t)(ty * 4 + i) * HID + tx + 16 * j] = acc[i][j] * inv;
    }
}

// ---------------------------------------------------------------------------
extern "C" void kernel_launch(void* const* d_in, const int* in_sizes, int n_in,
                              void* d_out, int out_size)
{
    const float* x  = (const float*)d_in[0];
    const float* wq = (const float*)d_in[1];
    const float* wk = (const float*)d_in[2];
    const float* wv = (const float*)d_in[3];
    const float* wo = (const float*)d_in[4];
    float* out = (float*)d_out;

    float *q, *k, *v, *o;
    cudaGetSymbolAddress((void**)&q, g_q);
    cudaGetSymbolAddress((void**)&k, g_k);
    cudaGetSymbolAddress((void**)&v, g_v);
    cudaGetSymbolAddress((void**)&o, g_o);

    dim3 blk(256);

    // Projections
    gemm_abt<<<dim3(HID / 128, MROWS / 128), blk>>>(x, wq, q, MROWS, HID, HID);
    gemm_abt<<<dim3(HD  / 128, MROWS / 128), blk>>>(x, wk, k, MROWS, HD,  HID);
    gemm_abt<<<dim3(HD  / 128, MROWS / 128), blk>>>(x, wv, v, MROWS, HD,  HID);

    // Flash attention
    size_t smem = (size_t)(3 * 64 * KPAD + 64 * PPAD) * sizeof(float);  // ~113 KB
    cudaFuncSetAttribute(flash_mqa, cudaFuncAttributeMaxDynamicSharedMemorySize,
                         (int)smem);
    flash_mqa<<<dim3(BATCH * NH, SEQ / 64), blk, smem>>>(q, k, v, o);

    // Output projection
    gemm_abt<<<dim3(HID / 128, MROWS / 128), blk>>>(o, wo, out, MROWS, HID, HID);
}

// round 3
// speedup vs baseline: 1.7231x; 1.7231x over previous
#include <cuda_runtime.h>
#include <cuda_bf16.h>
#include <cstdint>

#define HID   2048
#define HD    128
#define NH    16
#define BATCH 2
#define SEQ   2048
#define MROWS (BATCH*SEQ)   // 4096

// Scratch buffers (no allocation allowed -> __device__ globals)
__device__ float g_q[(size_t)MROWS * HID];
__device__ float g_k[(size_t)MROWS * HD];
__device__ float g_v[(size_t)MROWS * HD];
__device__ float g_o[(size_t)MROWS * HID];

__device__ __forceinline__ uint32_t cvt_tf32(float x) {
    uint32_t r; asm("cvt.rna.tf32.f32 %0, %1;" : "=r"(r) : "f"(x)); return r;
}

__device__ __forceinline__ void mma_tf32(float* d, const uint32_t* a,
                                         const uint32_t* b, const float* c) {
    asm volatile(
        "mma.sync.aligned.m16n8k8.row.col.f32.tf32.tf32.f32 "
        "{%0,%1,%2,%3}, {%4,%5,%6,%7}, {%8,%9}, {%10,%11,%12,%13};"
        : "=f"(d[0]), "=f"(d[1]), "=f"(d[2]), "=f"(d[3])
        : "r"(a[0]), "r"(a[1]), "r"(a[2]), "r"(a[3]),
          "r"(b[0]), "r"(b[1]),
          "f"(c[0]), "f"(c[1]), "f"(c[2]), "f"(c[3]));
}

// ===========================================================================
// tf32 mma.sync GEMM: C[M,N] = A[M,K] * B[N,K]^T
// 128x128 CTA tile, BK=32, 256 threads (8 warps, 2M x 4N), warp tile 64x32.
// Register-prefetch pipeline; cvt.rna.tf32 on the SMEM-store path.
// SMEM row stride PAD=36 floats -> fragment reads are bank-conflict-free.
// ===========================================================================
#define BK   32
#define PAD  36

__global__ __launch_bounds__(256, 2) void gemm_tf32(
    const float* __restrict__ A, const float* __restrict__ B,
    float* __restrict__ C, int M, int N, int K)
{
    __shared__ uint32_t As[128 * PAD];
    __shared__ uint32_t Bs[128 * PAD];

    const int tid  = threadIdx.x;
    const int wid  = tid >> 5;
    const int lane = tid & 31;
    const int grp  = lane >> 2;       // 0..7
    const int tg   = lane & 3;        // 0..3
    const int wm   = (wid & 1) * 64;  // warp M offset
    const int wn   = (wid >> 1) * 32; // warp N offset
    const int m0 = blockIdx.y * 128;
    const int n0 = blockIdx.x * 128;

    // gmem load mapping: 1024 float4s per (A|B) tile, 4 per thread
    const int ldr  = tid >> 3;        // base row 0..31 step via +32
    const int ldc  = (tid & 7) * 4;   // float col 0..28

    float acc[4][4][4];
#pragma unroll
    for (int i = 0; i < 4; i++)
#pragma unroll
        for (int j = 0; j < 4; j++)
#pragma unroll
            for (int r = 0; r < 4; r++) acc[i][j][r] = 0.f;

    const int nchunks = K / BK;
    float4 pa[4], pb[4];

    // Preload chunk 0
#pragma unroll
    for (int it = 0; it < 4; it++) {
        int r = ldr + it * 32;
        pa[it] = *(const float4*)&A[(size_t)(m0 + r) * K + ldc];
        pb[it] = *(const float4*)&B[(size_t)(n0 + r) * K + ldc];
    }

    for (int c = 0; c < nchunks; c++) {
        // Store prefetched chunk to SMEM (with tf32 rounding)
#pragma unroll
        for (int it = 0; it < 4; it++) {
            int r = ldr + it * 32;
            As[r * PAD + ldc + 0] = cvt_tf32(pa[it].x);
            As[r * PAD + ldc + 1] = cvt_tf32(pa[it].y);
            As[r * PAD + ldc + 2] = cvt_tf32(pa[it].z);
            As[r * PAD + ldc + 3] = cvt_tf32(pa[it].w);
            Bs[r * PAD + ldc + 0] = cvt_tf32(pb[it].x);
            Bs[r * PAD + ldc + 1] = cvt_tf32(pb[it].y);
            Bs[r * PAD + ldc + 2] = cvt_tf32(pb[it].z);
            Bs[r * PAD + ldc + 3] = cvt_tf32(pb[it].w);
        }
        __syncthreads();

        // Prefetch next chunk (overlaps with MMA compute below)
        if (c + 1 < nchunks) {
            const int k0 = (c + 1) * BK;
#pragma unroll
            for (int it = 0; it < 4; it++) {
                int r = ldr + it * 32;
                pa[it] = *(const float4*)&A[(size_t)(m0 + r) * K + k0 + ldc];
                pb[it] = *(const float4*)&B[(size_t)(n0 + r) * K + k0 + ldc];
            }
        }

        // Compute: 4 k-steps of 8
#pragma unroll
        for (int ks = 0; ks < 4; ks++) {
            const int k0 = ks * 8;
            uint32_t afr[4][4], bfr[4][2];
#pragma unroll
            for (int mf = 0; mf < 4; mf++) {
                int row = wm + mf * 16 + grp;
                afr[mf][0] = As[row * PAD + k0 + tg];
                afr[mf][1] = As[(row + 8) * PAD + k0 + tg];
                afr[mf][2] = As[row * PAD + k0 + tg + 4];
                afr[mf][3] = As[(row + 8) * PAD + k0 + tg + 4];
            }
#pragma unroll
            for (int nf = 0; nf < 4; nf++) {
                int col = wn + nf * 8 + grp;
                bfr[nf][0] = Bs[col * PAD + k0 + tg];
                bfr[nf][1] = Bs[col * PAD + k0 + tg + 4];
            }
#pragma unroll
            for (int mf = 0; mf < 4; mf++)
#pragma unroll
                for (int nf = 0; nf < 4; nf++)
                    mma_tf32(acc[mf][nf], afr[mf], bfr[nf], acc[mf][nf]);
        }
        __syncthreads();
    }

    // Epilogue: write C fragments (float2 per half-fragment row)
#pragma unroll
    for (int mf = 0; mf < 4; mf++) {
#pragma unroll
        for (int nf = 0; nf < 4; nf++) {
            int row = m0 + wm + mf * 16 + grp;
            int col = n0 + wn + nf * 8 + tg * 2;
            *(float2*)&C[(size_t)row * N + col] =
                make_float2(acc[mf][nf][0], acc[mf][nf][1]);
            *(float2*)&C[(size_t)(row + 8) * N + col] =
                make_float2(acc[mf][nf][2], acc[mf][nf][3]);
        }
    }
}

// ===========================================================================
// Flash-attention MQA (fp32 SIMT, unchanged)
// ===========================================================================
#define KPAD 129
#define PPAD 65

__global__ __launch_bounds__(256) void flash_mqa(
    const float* __restrict__ Q, const float* __restrict__ Kg,
    const float* __restrict__ Vg, float* __restrict__ O)
{
    extern __shared__ float sm[];
    float* Qs = sm;
    float* Ks = Qs + 64 * KPAD;
    float* Vs = Ks + 64 * KPAD;
    float* Ps = Vs + 64 * KPAD;

    const int tid = threadIdx.x;
    const int tx = tid & 15;
    const int ty = tid >> 4;
    const int b  = blockIdx.x >> 4;
    const int h  = blockIdx.x & 15;
    const int q0 = blockIdx.y * 64;
    const float scale = 0.08838834764831845f;

    const float* qbase = Q + ((size_t)(b * SEQ + q0)) * HID + h * HD;
#pragma unroll
    for (int it = 0; it < 8; it++) {
        int idx4 = tid + it * 256;
        int r  = idx4 >> 5;
        int c4 = (idx4 & 31) * 4;
        float4 v = *(const float4*)&qbase[(size_t)r * HID + c4];
        Qs[r * KPAD + c4 + 0] = v.x; Qs[r * KPAD + c4 + 1] = v.y;
        Qs[r * KPAD + c4 + 2] = v.z; Qs[r * KPAD + c4 + 3] = v.w;
    }

    float m[4], l[4], acc[4][8];
#pragma unroll
    for (int i = 0; i < 4; i++) {
        m[i] = -1e30f; l[i] = 0.f;
#pragma unroll
        for (int j = 0; j < 8; j++) acc[i][j] = 0.f;
    }
    __syncthreads();

    const float* kbase = Kg + (size_t)b * SEQ * HD;
    const float* vbase = Vg + (size_t)b * SEQ * HD;

    for (int t0 = 0; t0 < SEQ; t0 += 64) {
#pragma unroll
        for (int it = 0; it < 8; it++) {
            int idx4 = tid + it * 256;
            int r  = idx4 >> 5;
            int c4 = (idx4 & 31) * 4;
            float4 kv = *(const float4*)&kbase[(size_t)(t0 + r) * HD + c4];
            float4 vv = *(const float4*)&vbase[(size_t)(t0 + r) * HD + c4];
            Ks[r * KPAD + c4 + 0] = kv.x; Ks[r * KPAD + c4 + 1] = kv.y;
            Ks[r * KPAD + c4 + 2] = kv.z; Ks[r * KPAD + c4 + 3] = kv.w;
            Vs[r * KPAD + c4 + 0] = vv.x; Vs[r * KPAD + c4 + 1] = vv.y;
            Vs[r * KPAD + c4 + 2] = vv.z; Vs[r * KPAD + c4 + 3] = vv.w;
        }
        __syncthreads();

        float s[4][4];
#pragma unroll
        for (int i = 0; i < 4; i++)
#pragma unroll
            for (int j = 0; j < 4; j++) s[i][j] = 0.f;

        for (int k = 0; k < HD; k++) {
            float rq[4], rk[4];
#pragma unroll
            for (int i = 0; i < 4; i++) rq[i] = Qs[(ty * 4 + i) * KPAD + k];
#pragma unroll
            for (int j = 0; j < 4; j++) rk[j] = Ks[(tx + 16 * j) * KPAD + k];
#pragma unroll
            for (int i = 0; i < 4; i++)
#pragma unroll
                for (int j = 0; j < 4; j++) s[i][j] += rq[i] * rk[j];
        }

#pragma unroll
        for (int i = 0; i < 4; i++) {
            float mloc = fmaxf(fmaxf(s[i][0] * scale, s[i][1] * scale),
                               fmaxf(s[i][2] * scale, s[i][3] * scale));
#pragma unroll
            for (int o = 1; o < 16; o <<= 1)
                mloc = fmaxf(mloc, __shfl_xor_sync(0xffffffffu, mloc, o));
            float mn    = fmaxf(m[i], mloc);
            float alpha = __expf(m[i] - mn);
            float ps = 0.f;
#pragma unroll
            for (int j = 0; j < 4; j++) {
                float p = __expf(s[i][j] * scale - mn);
                s[i][j] = p;
                ps += p;
            }
#pragma unroll
            for (int o = 1; o < 16; o <<= 1)
                ps += __shfl_xor_sync(0xffffffffu, ps, o);
            l[i] = l[i] * alpha + ps;
            m[i] = mn;
#pragma unroll
            for (int j = 0; j < 8; j++) acc[i][j] *= alpha;
#pragma unroll
            for (int j = 0; j < 4; j++)
                Ps[(ty * 4 + i) * PPAD + tx + 16 * j] = s[i][j];
        }
        __syncthreads();

        for (int t = 0; t < 64; t++) {
            float rv[8];
#pragma unroll
            for (int j = 0; j < 8; j++) rv[j] = Vs[t * KPAD + tx + 16 * j];
#pragma unroll
            for (int i = 0; i < 4; i++) {
                float p = Ps[(ty * 4 + i) * PPAD + t];
#pragma unroll
                for (int j = 0; j < 8; j++) acc[i][j] += p * rv[j];
            }
        }
        __syncthreads();
    }

    float* obase = O + ((size_t)(b * SEQ + q0)) * HID + h * HD;
#pragma unroll
    for (int i = 0; i < 4; i++) {
        float inv = 1.f / l[i];
#pragma unroll
        for (int j = 0; j < 8; j++)
            obase[(size_t)(ty * 4 + i) * HID + tx + 16 * j] = acc[i][j] * inv;
    }
}

// ===========================================================================
extern "C" void kernel_launch(void* const* d_in, const int* in_sizes, int n_in,
                              void* d_out, int out_size)
{
    const float* x  = (const float*)d_in[0];
    const float* wq = (const float*)d_in[1];
    const float* wk = (const float*)d_in[2];
    const float* wv = (const float*)d_in[3];
    const float* wo = (const float*)d_in[4];
    float* out = (float*)d_out;

    float *q, *k, *v, *o;
    cudaGetSymbolAddress((void**)&q, g_q);
    cudaGetSymbolAddress((void**)&k, g_k);
    cudaGetSymbolAddress((void**)&v, g_v);
    cudaGetSymbolAddress((void**)&o, g_o);

    size_t fs = (size_t)(3 * 64 * KPAD + 64 * PPAD) * sizeof(float);
    cudaFuncSetAttribute(flash_mqa, cudaFuncAttributeMaxDynamicSharedMemorySize,
                         (int)fs);

    dim3 blk(256);

    // Projections (tensor-core tf32 mma.sync)
    gemm_tf32<<<dim3(HID / 128, MROWS / 128), blk>>>(x, wq, q, MROWS, HID, HID);
    gemm_tf32<<<dim3(HD  / 128, MROWS / 128), blk>>>(x, wk, k, MROWS, HD,  HID);
    gemm_tf32<<<dim3(HD  / 128, MROWS / 128), blk>>>(x, wv, v, MROWS, HD,  HID);

    // Flash attention (fp32 SIMT)
    flash_mqa<<<dim3(BATCH * NH, SEQ / 64), blk, fs>>>(q, k, v, o);

    // Output projection (tensor-core tf32 mma.sync)
    gemm_tf32<<<dim3(HID / 128, MROWS / 128), blk>>>(o, wo, out, MROWS, HID, HID);
}

// round 5
// speedup vs baseline: 4.2709x; 2.4786x over previous
#include <cuda_runtime.h>
#include <cuda_bf16.h>
#include <cstdint>

#define HID   2048
#define HD    128
#define NH    16
#define BATCH 2
#define SEQ   2048
#define MROWS (BATCH*SEQ)   // 4096

__device__ float g_q[(size_t)MROWS * HID];
__device__ float g_k[(size_t)MROWS * HD];
__device__ float g_v[(size_t)MROWS * HD];
__device__ float g_o[(size_t)MROWS * HID];

__device__ __forceinline__ uint32_t cvt_tf32(float x) {
    uint32_t r; asm("cvt.rna.tf32.f32 %0, %1;" : "=r"(r) : "f"(x)); return r;
}

__device__ __forceinline__ void mma_tf32(float* d, const uint32_t* a,
                                         const uint32_t* b, const float* c) {
    asm volatile(
        "mma.sync.aligned.m16n8k8.row.col.f32.tf32.tf32.f32 "
        "{%0,%1,%2,%3}, {%4,%5,%6,%7}, {%8,%9}, {%10,%11,%12,%13};"
        : "=f"(d[0]), "=f"(d[1]), "=f"(d[2]), "=f"(d[3])
        : "r"(a[0]), "r"(a[1]), "r"(a[2]), "r"(a[3]),
          "r"(b[0]), "r"(b[1]),
          "f"(c[0]), "f"(c[1]), "f"(c[2]), "f"(c[3]));
}

__device__ __forceinline__ void cp16(uint32_t dst, const void* src) {
    asm volatile("cp.async.ca.shared.global [%0], [%1], 16;" :: "r"(dst), "l"(src));
}
#define CP_COMMIT() asm volatile("cp.async.commit_group;" ::: "memory")
#define CP_WAIT(n)  asm volatile("cp.async.wait_group %0;" :: "n"(n) : "memory")

__device__ __forceinline__ uint32_t smem_u32(const void* p) {
    uint32_t a;
    asm("{ .reg .u64 t; cvta.to.shared.u64 t, %1; cvt.u32.u64 %0, t; }"
        : "=r"(a) : "l"(p));
    return a;
}

// ===========================================================================
// tf32 mma.sync GEMM: C[M,N] = A[M,K] * B[N,K]^T  (optionally tf32-rounded out)
// If B2/C2 non-null, blockIdx.z==1 computes C2 = A * B2^T (fused K/V proj).
// ===========================================================================
#define BK   32
#define PAD  36

__global__ __launch_bounds__(256, 2) void gemm_tf32(
    const float* __restrict__ A, const float* __restrict__ B,
    float* __restrict__ C, int M, int N, int K, int round_out,
    const float* __restrict__ B2, float* __restrict__ C2)
{
    __shared__ uint32_t As[128 * PAD];
    __shared__ uint32_t Bs[128 * PAD];

    if (blockIdx.z == 1) { B = B2; C = C2; }

    const int tid  = threadIdx.x;
    const int wid  = tid >> 5;
    const int lane = tid & 31;
    const int grp  = lane >> 2;
    const int tg   = lane & 3;
    const int wm   = (wid & 1) * 64;
    const int wn   = (wid >> 1) * 32;
    const int m0 = blockIdx.y * 128;
    const int n0 = blockIdx.x * 128;

    const int ldr  = tid >> 3;
    const int ldc  = (tid & 7) * 4;

    float acc[4][4][4];
#pragma unroll
    for (int i = 0; i < 4; i++)
#pragma unroll
        for (int j = 0; j < 4; j++)
#pragma unroll
            for (int r = 0; r < 4; r++) acc[i][j][r] = 0.f;

    const int nchunks = K / BK;
    float4 pa[4], pb[4];

#pragma unroll
    for (int it = 0; it < 4; it++) {
        int r = ldr + it * 32;
        pa[it] = *(const float4*)&A[(size_t)(m0 + r) * K + ldc];
        pb[it] = *(const float4*)&B[(size_t)(n0 + r) * K + ldc];
    }

    for (int c = 0; c < nchunks; c++) {
#pragma unroll
        for (int it = 0; it < 4; it++) {
            int r = ldr + it * 32;
            As[r * PAD + ldc + 0] = cvt_tf32(pa[it].x);
            As[r * PAD + ldc + 1] = cvt_tf32(pa[it].y);
            As[r * PAD + ldc + 2] = cvt_tf32(pa[it].z);
            As[r * PAD + ldc + 3] = cvt_tf32(pa[it].w);
            Bs[r * PAD + ldc + 0] = cvt_tf32(pb[it].x);
            Bs[r * PAD + ldc + 1] = cvt_tf32(pb[it].y);
            Bs[r * PAD + ldc + 2] = cvt_tf32(pb[it].z);
            Bs[r * PAD + ldc + 3] = cvt_tf32(pb[it].w);
        }
        __syncthreads();

        if (c + 1 < nchunks) {
            const int k0 = (c + 1) * BK;
#pragma unroll
            for (int it = 0; it < 4; it++) {
                int r = ldr + it * 32;
                pa[it] = *(const float4*)&A[(size_t)(m0 + r) * K + k0 + ldc];
                pb[it] = *(const float4*)&B[(size_t)(n0 + r) * K + k0 + ldc];
            }
        }

#pragma unroll
        for (int ks = 0; ks < 4; ks++) {
            const int k0 = ks * 8;
            uint32_t afr[4][4], bfr[4][2];
#pragma unroll
            for (int mf = 0; mf < 4; mf++) {
                int row = wm + mf * 16 + grp;
                afr[mf][0] = As[row * PAD + k0 + tg];
                afr[mf][1] = As[(row + 8) * PAD + k0 + tg];
                afr[mf][2] = As[row * PAD + k0 + tg + 4];
                afr[mf][3] = As[(row + 8) * PAD + k0 + tg + 4];
            }
#pragma unroll
            for (int nf = 0; nf < 4; nf++) {
                int col = wn + nf * 8 + grp;
                bfr[nf][0] = Bs[col * PAD + k0 + tg];
                bfr[nf][1] = Bs[col * PAD + k0 + tg + 4];
            }
#pragma unroll
            for (int mf = 0; mf < 4; mf++)
#pragma unroll
                for (int nf = 0; nf < 4; nf++)
                    mma_tf32(acc[mf][nf], afr[mf], bfr[nf], acc[mf][nf]);
        }
        __syncthreads();
    }

#pragma unroll
    for (int mf = 0; mf < 4; mf++) {
#pragma unroll
        for (int nf = 0; nf < 4; nf++) {
            int row = m0 + wm + mf * 16 + grp;
            int col = n0 + wn + nf * 8 + tg * 2;
            float v0 = acc[mf][nf][0], v1 = acc[mf][nf][1];
            float v2 = acc[mf][nf][2], v3 = acc[mf][nf][3];
            if (round_out) {
                v0 = __uint_as_float(cvt_tf32(v0));
                v1 = __uint_as_float(cvt_tf32(v1));
                v2 = __uint_as_float(cvt_tf32(v2));
                v3 = __uint_as_float(cvt_tf32(v3));
            }
            *(float2*)&C[(size_t)row * N + col] = make_float2(v0, v1);
            *(float2*)&C[(size_t)(row + 8) * N + col] = make_float2(v2, v3);
        }
    }
}

// ===========================================================================
// Tensor-core flash MQA. CTA = (b, h, 128 queries); 8 warps x 16 q-rows.
// Key blocks of 64; K/V double-buffered via cp.async; Q fragments in regs
// (inputs pre-rounded to tf32 by the projection epilogue -> exact tf32 MMA).
// ===========================================================================
#define BQ    128
#define BKEY  64
#define PADK  132
#define PADV  136
#define PADP  68
#define OFF_K0 0
#define OFF_K1 8448
#define OFF_V0 16896
#define OFF_V1 25600
#define OFF_P  34304
#define FLASH_SMEM (43008 * 4)

__global__ __launch_bounds__(256, 1) void flash_mqa_tc(
    const float* __restrict__ Q, const float* __restrict__ Kg,
    const float* __restrict__ Vg, float* __restrict__ O)
{
    extern __shared__ float sm[];
    const uint32_t sb = smem_u32(sm);
    const int tid = threadIdx.x;
    const int wid = tid >> 5;
    const int lane = tid & 31;
    const int grp = lane >> 2;
    const int tg  = lane & 3;
    const int h = blockIdx.x & 15;
    const int b = blockIdx.x >> 4;
    const int q0 = blockIdx.y * BQ;
    const float scale = 0.08838834764831845f;   // 1/sqrt(128)

    const float* kb = Kg + (size_t)b * SEQ * HD;
    const float* vb = Vg + (size_t)b * SEQ * HD;

    // Q fragments: warp rows q0 + wid*16 + {grp, grp+8}, 16 k-tiles of 8
    uint32_t qf[16][4];
    {
        const float* qbase = Q + (size_t)(b * SEQ + q0 + wid * 16) * HID + h * HD;
#pragma unroll
        for (int ks = 0; ks < 16; ks++) {
            qf[ks][0] = __float_as_uint(qbase[(size_t)grp * HID + ks * 8 + tg]);
            qf[ks][1] = __float_as_uint(qbase[(size_t)(grp + 8) * HID + ks * 8 + tg]);
            qf[ks][2] = __float_as_uint(qbase[(size_t)grp * HID + ks * 8 + tg + 4]);
            qf[ks][3] = __float_as_uint(qbase[(size_t)(grp + 8) * HID + ks * 8 + tg + 4]);
        }
    }

    float o[16][4];
#pragma unroll
    for (int i = 0; i < 16; i++)
#pragma unroll
        for (int j = 0; j < 4; j++) o[i][j] = 0.f;
    float m0r = -1e30f, m1r = -1e30f, l0 = 0.f, l1 = 0.f;

    // Prefetch key block 0 into buffer 0
    {
#pragma unroll
        for (int it = 0; it < 8; it++) {
            int idx = tid + it * 256;
            int r = idx >> 5, ch = (idx & 31) * 4;
            cp16(sb + (OFF_K0 + r * PADK + ch) * 4, kb + (size_t)r * HD + ch);
            cp16(sb + (OFF_V0 + r * PADV + ch) * 4, vb + (size_t)r * HD + ch);
        }
        CP_COMMIT();
    }

    const int nb = SEQ / BKEY;   // 32
    for (int blk = 0; blk < nb; blk++) {
        const int cur = blk & 1;
        if (blk + 1 < nb) {
            const float* kn = kb + (size_t)(blk + 1) * BKEY * HD;
            const float* vn = vb + (size_t)(blk + 1) * BKEY * HD;
            const uint32_t ko = (cur ? OFF_K0 : OFF_K1);
            const uint32_t vo = (cur ? OFF_V0 : OFF_V1);
#pragma unroll
            for (int it = 0; it < 8; it++) {
                int idx = tid + it * 256;
                int r = idx >> 5, ch = (idx & 31) * 4;
                cp16(sb + (ko + r * PADK + ch) * 4, kn + (size_t)r * HD + ch);
                cp16(sb + (vo + r * PADV + ch) * 4, vn + (size_t)r * HD + ch);
            }
            CP_COMMIT();
            CP_WAIT(1);
        } else {
            CP_WAIT(0);
        }
        __syncthreads();

        const float* Kp = sm + (cur ? OFF_K1 : OFF_K0);
        const float* Vp = sm + (cur ? OFF_V1 : OFF_V0);
        float* Pp = sm + OFF_P + (size_t)(wid * 16) * PADP;

        // ---- S = Q * K^T : 8 n-tiles (64 keys) x 16 k-steps ----
        float s[8][4];
#pragma unroll
        for (int nt = 0; nt < 8; nt++)
#pragma unroll
            for (int j = 0; j < 4; j++) s[nt][j] = 0.f;

#pragma unroll
        for (int ks = 0; ks < 16; ks++) {
            uint32_t bf[8][2];
#pragma unroll
            for (int nt = 0; nt < 8; nt++) {
                bf[nt][0] = __float_as_uint(Kp[(nt * 8 + grp) * PADK + ks * 8 + tg]);
                bf[nt][1] = __float_as_uint(Kp[(nt * 8 + grp) * PADK + ks * 8 + tg + 4]);
            }
#pragma unroll
            for (int nt = 0; nt < 8; nt++)
                mma_tf32(s[nt], qf[ks], bf[nt], s[nt]);
        }

        // ---- online softmax (rows grp, grp+8; quad reduce over tg) ----
        float ml0 = -1e30f, ml1 = -1e30f;
#pragma unroll
        for (int nt = 0; nt < 8; nt++) {
            ml0 = fmaxf(ml0, fmaxf(s[nt][0], s[nt][1]));
            ml1 = fmaxf(ml1, fmaxf(s[nt][2], s[nt][3]));
        }
        ml0 *= scale; ml1 *= scale;
#pragma unroll
        for (int off = 1; off < 4; off <<= 1) {
            ml0 = fmaxf(ml0, __shfl_xor_sync(0xffffffffu, ml0, off));
            ml1 = fmaxf(ml1, __shfl_xor_sync(0xffffffffu, ml1, off));
        }
        const float mn0 = fmaxf(m0r, ml0);
        const float mn1 = fmaxf(m1r, ml1);
        const float a0 = __expf(m0r - mn0);
        const float a1 = __expf(m1r - mn1);
        float sum0 = 0.f, sum1 = 0.f;
#pragma unroll
        for (int nt = 0; nt < 8; nt++) {
            float p00 = __expf(s[nt][0] * scale - mn0);
            float p01 = __expf(s[nt][1] * scale - mn0);
            float p10 = __expf(s[nt][2] * scale - mn1);
            float p11 = __expf(s[nt][3] * scale - mn1);
            sum0 += p00 + p01;
            sum1 += p10 + p11;
            Pp[(size_t)grp * PADP + nt * 8 + 2 * tg]     = __uint_as_float(cvt_tf32(p00));
            Pp[(size_t)grp * PADP + nt * 8 + 2 * tg + 1] = __uint_as_float(cvt_tf32(p01));
            Pp[(size_t)(grp + 8) * PADP + nt * 8 + 2 * tg]     = __uint_as_float(cvt_tf32(p10));
            Pp[(size_t)(grp + 8) * PADP + nt * 8 + 2 * tg + 1] = __uint_as_float(cvt_tf32(p11));
        }
#pragma unroll
        for (int off = 1; off < 4; off <<= 1) {
            sum0 += __shfl_xor_sync(0xffffffffu, sum0, off);
            sum1 += __shfl_xor_sync(0xffffffffu, sum1, off);
        }
        l0 = l0 * a0 + sum0;
        l1 = l1 * a1 + sum1;
        m0r = mn0; m1r = mn1;
#pragma unroll
        for (int nt = 0; nt < 16; nt++) {
            o[nt][0] *= a0; o[nt][1] *= a0;
            o[nt][2] *= a1; o[nt][3] *= a1;
        }
        __syncwarp();

        // ---- O += P * V : 8 key k-steps x 16 d-tiles ----
#pragma unroll
        for (int ks2 = 0; ks2 < 8; ks2++) {
            uint32_t af[4];
            af[0] = __float_as_uint(Pp[(size_t)grp * PADP + ks2 * 8 + tg]);
            af[1] = __float_as_uint(Pp[(size_t)(grp + 8) * PADP + ks2 * 8 + tg]);
            af[2] = __float_as_uint(Pp[(size_t)grp * PADP + ks2 * 8 + tg + 4]);
            af[3] = __float_as_uint(Pp[(size_t)(grp + 8) * PADP + ks2 * 8 + tg + 4]);
#pragma unroll
            for (int nt = 0; nt < 16; nt++) {
                uint32_t bf2[2];
                bf2[0] = __float_as_uint(Vp[(ks2 * 8 + tg) * PADV + nt * 8 + grp]);
                bf2[1] = __float_as_uint(Vp[(ks2 * 8 + tg + 4) * PADV + nt * 8 + grp]);
                mma_tf32(o[nt], af, bf2, o[nt]);
            }
        }
        __syncthreads();
    }

    // ---- epilogue ----
    const float inv0 = 1.f / l0;
    const float inv1 = 1.f / l1;
    float* ob = O + (size_t)(b * SEQ + q0 + wid * 16) * HID + h * HD;
#pragma unroll
    for (int nt = 0; nt < 16; nt++) {
        int c = nt * 8 + 2 * tg;
        *(float2*)&ob[(size_t)grp * HID + c] =
            make_float2(o[nt][0] * inv0, o[nt][1] * inv0);
        *(float2*)&ob[(size_t)(grp + 8) * HID + c] =
            make_float2(o[nt][2] * inv1, o[nt][3] * inv1);
    }
}

// ===========================================================================
extern "C" void kernel_launch(void* const* d_in, const int* in_sizes, int n_in,
                              void* d_out, int out_size)
{
    const float* x  = (const float*)d_in[0];
    const float* wq = (const float*)d_in[1];
    const float* wk = (const float*)d_in[2];
    const float* wv = (const float*)d_in[3];
    const float* wo = (const float*)d_in[4];
    float* out = (float*)d_out;

    float *q, *k, *v, *o;
    cudaGetSymbolAddress((void**)&q, g_q);
    cudaGetSymbolAddress((void**)&k, g_k);
    cudaGetSymbolAddress((void**)&v, g_v);
    cudaGetSymbolAddress((void**)&o, g_o);

    cudaFuncSetAttribute(flash_mqa_tc,
                         cudaFuncAttributeMaxDynamicSharedMemorySize, FLASH_SMEM);

    dim3 blk(256);

    // Q projection (tf32-rounded output)
    gemm_tf32<<<dim3(HID / 128, MROWS / 128, 1), blk>>>(
        x, wq, q, MROWS, HID, HID, 1, nullptr, nullptr);
    // K and V projections fused into one launch via gridDim.z
    gemm_tf32<<<dim3(HD / 128, MROWS / 128, 2), blk>>>(
        x, wk, k, MROWS, HD, HID, 1, wv, v);

    // Tensor-core flash attention
    flash_mqa_tc<<<dim3(BATCH * NH, SEQ / BQ), blk, FLASH_SMEM>>>(q, k, v, o);

    // Output projection (full fp32 output)
    gemm_tf32<<<dim3(HID / 128, MROWS / 128, 1), blk>>>(
        o, wo, out, MROWS, HID, HID, 0, nullptr, nullptr);
}

// round 6
// speedup vs baseline: 4.5528x; 1.0660x over previous
#include <cuda_runtime.h>
#include <cuda_bf16.h>
#include <cstdint>

#define HID   2048
#define HD    128
#define NH    16
#define BATCH 2
#define SEQ   2048
#define MROWS (BATCH*SEQ)   // 4096

// Scratch (no allocation allowed -> __device__ globals)
__device__ float g_q[(size_t)MROWS * HID];
__device__ float g_k[(size_t)MROWS * HD];
__device__ float g_v[(size_t)MROWS * HD];
__device__ float g_o[(size_t)MROWS * HID];
__device__ float g_x[(size_t)MROWS * HID];   // tf32-rounded x
__device__ float g_wq[(size_t)HID * HID];    // tf32-rounded w_q
__device__ float g_wo[(size_t)HID * HID];    // tf32-rounded w_out

__device__ __forceinline__ uint32_t cvt_tf32(float x) {
    uint32_t r; asm("cvt.rna.tf32.f32 %0, %1;" : "=r"(r) : "f"(x)); return r;
}

__device__ __forceinline__ void mma_tf32(float* d, const uint32_t* a,
                                         const uint32_t* b, const float* c) {
    asm volatile(
        "mma.sync.aligned.m16n8k8.row.col.f32.tf32.tf32.f32 "
        "{%0,%1,%2,%3}, {%4,%5,%6,%7}, {%8,%9}, {%10,%11,%12,%13};"
        : "=f"(d[0]), "=f"(d[1]), "=f"(d[2]), "=f"(d[3])
        : "r"(a[0]), "r"(a[1]), "r"(a[2]), "r"(a[3]),
          "r"(b[0]), "r"(b[1]),
          "f"(c[0]), "f"(c[1]), "f"(c[2]), "f"(c[3]));
}

__device__ __forceinline__ void cp16(uint32_t dst, const void* src) {
    asm volatile("cp.async.ca.shared.global [%0], [%1], 16;" :: "r"(dst), "l"(src));
}
#define CP_COMMIT() asm volatile("cp.async.commit_group;" ::: "memory")
#define CP_WAIT(n)  asm volatile("cp.async.wait_group %0;" :: "n"(n) : "memory")

__device__ __forceinline__ uint32_t smem_u32(const void* p) {
    uint32_t a;
    asm("{ .reg .u64 t; cvta.to.shared.u64 t, %1; cvt.u32.u64 %0, t; }"
        : "=r"(a) : "l"(p));
    return a;
}

// ===========================================================================
// Pre-pass: RNA-round three arrays to tf32 (so cp.async paths carry exact tf32)
// ===========================================================================
__global__ void round3_tf32(const float* __restrict__ a, float* __restrict__ ao, int na4,
                            const float* __restrict__ b, float* __restrict__ bo, int nb4,
                            const float* __restrict__ c, float* __restrict__ co, int nc4)
{
    int total = na4 + nb4 + nc4;
    for (int i = blockIdx.x * blockDim.x + threadIdx.x; i < total;
         i += gridDim.x * blockDim.x) {
        const float4* src; float4* dst; int j = i;
        if (j < na4) { src = (const float4*)a; dst = (float4*)ao; }
        else if ((j -= na4) < nb4) { src = (const float4*)b; dst = (float4*)bo; }
        else { j -= nb4; src = (const float4*)c; dst = (float4*)co; }
        float4 v = src[j];
        v.x = __uint_as_float(cvt_tf32(v.x));
        v.y = __uint_as_float(cvt_tf32(v.y));
        v.z = __uint_as_float(cvt_tf32(v.z));
        v.w = __uint_as_float(cvt_tf32(v.w));
        dst[j] = v;
    }
}

// ===========================================================================
// Wide tf32 GEMM: C[M,N] = A[M,K] * B[N,K]^T. CTA 128x256, 8 warps of 64x64.
// Inputs must already be tf32-valued. cp.async double-buffered, BK=32.
// ===========================================================================
#define WPAD  36
#define WASZ  (128 * WPAD)              // A stage floats
#define WBSZ  (256 * WPAD)              // B stage floats
#define WSTG  (WASZ + WBSZ)             // one stage
#define WSMEM (2 * WSTG * 4)            // bytes = 110592

__global__ __launch_bounds__(256, 1) void gemm_wide(
    const float* __restrict__ A, const float* __restrict__ B,
    float* __restrict__ C, int M, int N, int K, int round_out)
{
    extern __shared__ float smf[];
    const uint32_t sb = smem_u32(smf);
    const int tid  = threadIdx.x;
    const int wid  = tid >> 5;
    const int lane = tid & 31;
    const int grp  = lane >> 2;
    const int tg   = lane & 3;
    const int wm   = (wid & 1) * 64;
    const int wn   = (wid >> 1) * 64;
    const int m0 = blockIdx.y * 128;
    const int n0 = blockIdx.x * 256;

    float acc[4][8][4];
#pragma unroll
    for (int i = 0; i < 4; i++)
#pragma unroll
        for (int j = 0; j < 8; j++)
#pragma unroll
            for (int r = 0; r < 4; r++) acc[i][j][r] = 0.f;

    const int nch = K / 32;

    // Stage loader: A 1024 granules, B 2048 granules, 256 threads
    auto load_stage = [&](int c, int buf) {
        const int k0 = c * 32;
        const uint32_t base = sb + buf * WSTG * 4;
#pragma unroll
        for (int i = 0; i < 4; i++) {
            int g = tid + i * 256;
            int r = g >> 3, c4 = (g & 7) * 4;
            cp16(base + (r * WPAD + c4) * 4, &A[(size_t)(m0 + r) * K + k0 + c4]);
        }
#pragma unroll
        for (int i = 0; i < 8; i++) {
            int g = tid + i * 256;
            int r = g >> 3, c4 = (g & 7) * 4;
            cp16(base + (WASZ + r * WPAD + c4) * 4, &B[(size_t)(n0 + r) * K + k0 + c4]);
        }
        CP_COMMIT();
    };

    load_stage(0, 0);

    for (int c = 0; c < nch; c++) {
        CP_WAIT(0);
        __syncthreads();
        if (c + 1 < nch) load_stage(c + 1, (c + 1) & 1);

        const float* sA = smf + (c & 1) * WSTG;
        const float* sB = sA + WASZ;

#pragma unroll
        for (int ks = 0; ks < 4; ks++) {
            const int k0 = ks * 8;
            uint32_t afr[4][4], bfr[8][2];
#pragma unroll
            for (int mf = 0; mf < 4; mf++) {
                int row = wm + mf * 16 + grp;
                afr[mf][0] = __float_as_uint(sA[row * WPAD + k0 + tg]);
                afr[mf][1] = __float_as_uint(sA[(row + 8) * WPAD + k0 + tg]);
                afr[mf][2] = __float_as_uint(sA[row * WPAD + k0 + tg + 4]);
                afr[mf][3] = __float_as_uint(sA[(row + 8) * WPAD + k0 + tg + 4]);
            }
#pragma unroll
            for (int nf = 0; nf < 8; nf++) {
                int col = wn + nf * 8 + grp;
                bfr[nf][0] = __float_as_uint(sB[col * WPAD + k0 + tg]);
                bfr[nf][1] = __float_as_uint(sB[col * WPAD + k0 + tg + 4]);
            }
#pragma unroll
            for (int mf = 0; mf < 4; mf++)
#pragma unroll
                for (int nf = 0; nf < 8; nf++)
                    mma_tf32(acc[mf][nf], afr[mf], bfr[nf], acc[mf][nf]);
        }
    }

#pragma unroll
    for (int mf = 0; mf < 4; mf++) {
#pragma unroll
        for (int nf = 0; nf < 8; nf++) {
            int row = m0 + wm + mf * 16 + grp;
            int col = n0 + wn + nf * 8 + tg * 2;
            float v0 = acc[mf][nf][0], v1 = acc[mf][nf][1];
            float v2 = acc[mf][nf][2], v3 = acc[mf][nf][3];
            if (round_out) {
                v0 = __uint_as_float(cvt_tf32(v0));
                v1 = __uint_as_float(cvt_tf32(v1));
                v2 = __uint_as_float(cvt_tf32(v2));
                v3 = __uint_as_float(cvt_tf32(v3));
            }
            *(float2*)&C[(size_t)row * N + col] = make_float2(v0, v1);
            *(float2*)&C[(size_t)(row + 8) * N + col] = make_float2(v2, v3);
        }
    }
}

// ===========================================================================
// Small GEMM (K/V projections, N=128): unchanged round-5 kernel.
// ===========================================================================
#define BK   32
#define PAD  36

__global__ __launch_bounds__(256, 2) void gemm_tf32(
    const float* __restrict__ A, const float* __restrict__ B,
    float* __restrict__ C, int M, int N, int K, int round_out,
    const float* __restrict__ B2, float* __restrict__ C2)
{
    __shared__ uint32_t As[128 * PAD];
    __shared__ uint32_t Bs[128 * PAD];

    if (blockIdx.z == 1) { B = B2; C = C2; }

    const int tid  = threadIdx.x;
    const int wid  = tid >> 5;
    const int lane = tid & 31;
    const int grp  = lane >> 2;
    const int tg   = lane & 3;
    const int wm   = (wid & 1) * 64;
    const int wn   = (wid >> 1) * 32;
    const int m0 = blockIdx.y * 128;
    const int n0 = blockIdx.x * 128;

    const int ldr  = tid >> 3;
    const int ldc  = (tid & 7) * 4;

    float acc[4][4][4];
#pragma unroll
    for (int i = 0; i < 4; i++)
#pragma unroll
        for (int j = 0; j < 4; j++)
#pragma unroll
            for (int r = 0; r < 4; r++) acc[i][j][r] = 0.f;

    const int nchunks = K / BK;
    float4 pa[4], pb[4];

#pragma unroll
    for (int it = 0; it < 4; it++) {
        int r = ldr + it * 32;
        pa[it] = *(const float4*)&A[(size_t)(m0 + r) * K + ldc];
        pb[it] = *(const float4*)&B[(size_t)(n0 + r) * K + ldc];
    }

    for (int c = 0; c < nchunks; c++) {
#pragma unroll
        for (int it = 0; it < 4; it++) {
            int r = ldr + it * 32;
            As[r * PAD + ldc + 0] = cvt_tf32(pa[it].x);
            As[r * PAD + ldc + 1] = cvt_tf32(pa[it].y);
            As[r * PAD + ldc + 2] = cvt_tf32(pa[it].z);
            As[r * PAD + ldc + 3] = cvt_tf32(pa[it].w);
            Bs[r * PAD + ldc + 0] = cvt_tf32(pb[it].x);
            Bs[r * PAD + ldc + 1] = cvt_tf32(pb[it].y);
            Bs[r * PAD + ldc + 2] = cvt_tf32(pb[it].z);
            Bs[r * PAD + ldc + 3] = cvt_tf32(pb[it].w);
        }
        __syncthreads();

        if (c + 1 < nchunks) {
            const int k0 = (c + 1) * BK;
#pragma unroll
            for (int it = 0; it < 4; it++) {
                int r = ldr + it * 32;
                pa[it] = *(const float4*)&A[(size_t)(m0 + r) * K + k0 + ldc];
                pb[it] = *(const float4*)&B[(size_t)(n0 + r) * K + k0 + ldc];
            }
        }

#pragma unroll
        for (int ks = 0; ks < 4; ks++) {
            const int k0 = ks * 8;
            uint32_t afr[4][4], bfr[4][2];
#pragma unroll
            for (int mf = 0; mf < 4; mf++) {
                int row = wm + mf * 16 + grp;
                afr[mf][0] = As[row * PAD + k0 + tg];
                afr[mf][1] = As[(row + 8) * PAD + k0 + tg];
                afr[mf][2] = As[row * PAD + k0 + tg + 4];
                afr[mf][3] = As[(row + 8) * PAD + k0 + tg + 4];
            }
#pragma unroll
            for (int nf = 0; nf < 4; nf++) {
                int col = wn + nf * 8 + grp;
                bfr[nf][0] = Bs[col * PAD + k0 + tg];
                bfr[nf][1] = Bs[col * PAD + k0 + tg + 4];
            }
#pragma unroll
            for (int mf = 0; mf < 4; mf++)
#pragma unroll
                for (int nf = 0; nf < 4; nf++)
                    mma_tf32(acc[mf][nf], afr[mf], bfr[nf], acc[mf][nf]);
        }
        __syncthreads();
    }

#pragma unroll
    for (int mf = 0; mf < 4; mf++) {
#pragma unroll
        for (int nf = 0; nf < 4; nf++) {
            int row = m0 + wm + mf * 16 + grp;
            int col = n0 + wn + nf * 8 + tg * 2;
            float v0 = acc[mf][nf][0], v1 = acc[mf][nf][1];
            float v2 = acc[mf][nf][2], v3 = acc[mf][nf][3];
            if (round_out) {
                v0 = __uint_as_float(cvt_tf32(v0));
                v1 = __uint_as_float(cvt_tf32(v1));
                v2 = __uint_as_float(cvt_tf32(v2));
                v3 = __uint_as_float(cvt_tf32(v3));
            }
            *(float2*)&C[(size_t)row * N + col] = make_float2(v0, v1);
            *(float2*)&C[(size_t)(row + 8) * N + col] = make_float2(v2, v3);
        }
    }
}

// ===========================================================================
// Tensor-core flash MQA. K double-buffered, V single-buffered (load hidden
// behind next block's QK+softmax), P kept in registers (quad-shuffle remap).
// SMEM 102.4 KB. Epilogue rounds O to tf32 for the out-projection.
// ===========================================================================
#define BQ    128
#define BKEY  64
#define PADK  132
#define PADV  136
#define OFF_K0 0
#define OFF_K1 8448
#define OFF_V  16896
#define FLASH_SMEM (25600 * 4)

__global__ __launch_bounds__(256, 1) void flash_mqa_tc(
    const float* __restrict__ Q, const float* __restrict__ Kg,
    const float* __restrict__ Vg, float* __restrict__ O)
{
    extern __shared__ float sm[];
    const uint32_t sb = smem_u32(sm);
    const int tid = threadIdx.x;
    const int wid = tid >> 5;
    const int lane = tid & 31;
    const int grp = lane >> 2;
    const int tg  = lane & 3;
    const int h = blockIdx.x & 15;
    const int b = blockIdx.x >> 4;
    const int q0 = blockIdx.y * BQ;
    const float scale = 0.08838834764831845f;   // 1/sqrt(128)

    const float* kb = Kg + (size_t)b * SEQ * HD;
    const float* vb = Vg + (size_t)b * SEQ * HD;
    const int nb = SEQ / BKEY;   // 32

    auto load_k = [&](int blk, uint32_t koff) {
        const float* src = kb + (size_t)blk * BKEY * HD;
#pragma unroll
        for (int it = 0; it < 8; it++) {
            int idx = tid + it * 256;
            int r = idx >> 5, ch = (idx & 31) * 4;
            cp16(sb + (koff + r * PADK + ch) * 4, src + (size_t)r * HD + ch);
        }
    };
    auto load_v = [&](int blk) {
        const float* src = vb + (size_t)blk * BKEY * HD;
#pragma unroll
        for (int it = 0; it < 8; it++) {
            int idx = tid + it * 256;
            int r = idx >> 5, ch = (idx & 31) * 4;
            cp16(sb + (OFF_V + r * PADV + ch) * 4, src + (size_t)r * HD + ch);
        }
    };

    // Q fragments (tf32-valued already)
    uint32_t qf[16][4];
    {
        const float* qbase = Q + (size_t)(b * SEQ + q0 + wid * 16) * HID + h * HD;
#pragma unroll
        for (int ks = 0; ks < 16; ks++) {
            qf[ks][0] = __float_as_uint(qbase[(size_t)grp * HID + ks * 8 + tg]);
            qf[ks][1] = __float_as_uint(qbase[(size_t)(grp + 8) * HID + ks * 8 + tg]);
            qf[ks][2] = __float_as_uint(qbase[(size_t)grp * HID + ks * 8 + tg + 4]);
            qf[ks][3] = __float_as_uint(qbase[(size_t)(grp + 8) * HID + ks * 8 + tg + 4]);
        }
    }

    float o[16][4];
#pragma unroll
    for (int i = 0; i < 16; i++)
#pragma unroll
        for (int j = 0; j < 4; j++) o[i][j] = 0.f;
    float m0r = -1e30f, m1r = -1e30f, l0 = 0.f, l1 = 0.f;

    // Pipeline prologue: G0={K0,V0}, G1={K1}
    load_k(0, OFF_K0); load_v(0); CP_COMMIT();
    load_k(1, OFF_K1); CP_COMMIT();

    const int qsl  = (lane & ~3) | (tg >> 1);   // shuffle source lanes (quad)
    const int qsl2 = qsl + 2;

    for (int blk = 0; blk < nb; blk++) {
        CP_WAIT(1);            // K(blk), V(blk) ready; K(blk+1) may be in flight
        __syncthreads();

        const float* Kp = sm + ((blk & 1) ? OFF_K1 : OFF_K0);
        const float* Vp = sm + OFF_V;

        // ---- S = Q * K^T ----
        float s[8][4];
#pragma unroll
        for (int nt = 0; nt < 8; nt++)
#pragma unroll
            for (int j = 0; j < 4; j++) s[nt][j] = 0.f;

#pragma unroll
        for (int ks = 0; ks < 16; ks++) {
            uint32_t bf[8][2];
#pragma unroll
            for (int nt = 0; nt < 8; nt++) {
                bf[nt][0] = __float_as_uint(Kp[(nt * 8 + grp) * PADK + ks * 8 + tg]);
                bf[nt][1] = __float_as_uint(Kp[(nt * 8 + grp) * PADK + ks * 8 + tg + 4]);
            }
#pragma unroll
            for (int nt = 0; nt < 8; nt++)
                mma_tf32(s[nt], qf[ks], bf[nt], s[nt]);
        }

        // ---- online softmax; P kept in registers (tf32-rounded) ----
        float ml0 = -1e30f, ml1 = -1e30f;
#pragma unroll
        for (int nt = 0; nt < 8; nt++) {
            ml0 = fmaxf(ml0, fmaxf(s[nt][0], s[nt][1]));
            ml1 = fmaxf(ml1, fmaxf(s[nt][2], s[nt][3]));
        }
        ml0 *= scale; ml1 *= scale;
#pragma unroll
        for (int off = 1; off < 4; off <<= 1) {
            ml0 = fmaxf(ml0, __shfl_xor_sync(0xffffffffu, ml0, off));
            ml1 = fmaxf(ml1, __shfl_xor_sync(0xffffffffu, ml1, off));
        }
        const float mn0 = fmaxf(m0r, ml0);
        const float mn1 = fmaxf(m1r, ml1);
        const float a0 = __expf(m0r - mn0);
        const float a1 = __expf(m1r - mn1);
        float sum0 = 0.f, sum1 = 0.f;
        uint32_t pf[8][4];
#pragma unroll
        for (int nt = 0; nt < 8; nt++) {
            float p00 = __expf(s[nt][0] * scale - mn0);
            float p01 = __expf(s[nt][1] * scale - mn0);
            float p10 = __expf(s[nt][2] * scale - mn1);
            float p11 = __expf(s[nt][3] * scale - mn1);
            sum0 += p00 + p01;
            sum1 += p10 + p11;
            pf[nt][0] = cvt_tf32(p00); pf[nt][1] = cvt_tf32(p01);
            pf[nt][2] = cvt_tf32(p10); pf[nt][3] = cvt_tf32(p11);
        }
#pragma unroll
        for (int off = 1; off < 4; off <<= 1) {
            sum0 += __shfl_xor_sync(0xffffffffu, sum0, off);
            sum1 += __shfl_xor_sync(0xffffffffu, sum1, off);
        }
        l0 = l0 * a0 + sum0;
        l1 = l1 * a1 + sum1;
        m0r = mn0; m1r = mn1;
#pragma unroll
        for (int nt = 0; nt < 16; nt++) {
            o[nt][0] *= a0; o[nt][1] *= a0;
            o[nt][2] *= a1; o[nt][3] *= a1;
        }

        // ---- O += P * V : A-fragments from pf via quad shuffles ----
#pragma unroll
        for (int ks2 = 0; ks2 < 8; ks2++) {
            uint32_t e0, e1, af[4];
            e0 = __shfl_sync(0xffffffffu, pf[ks2][0], qsl);
            e1 = __shfl_sync(0xffffffffu, pf[ks2][1], qsl);
            af[0] = (tg & 1) ? e1 : e0;
            e0 = __shfl_sync(0xffffffffu, pf[ks2][2], qsl);
            e1 = __shfl_sync(0xffffffffu, pf[ks2][3], qsl);
            af[1] = (tg & 1) ? e1 : e0;
            e0 = __shfl_sync(0xffffffffu, pf[ks2][0], qsl2);
            e1 = __shfl_sync(0xffffffffu, pf[ks2][1], qsl2);
            af[2] = (tg & 1) ? e1 : e0;
            e0 = __shfl_sync(0xffffffffu, pf[ks2][2], qsl2);
            e1 = __shfl_sync(0xffffffffu, pf[ks2][3], qsl2);
            af[3] = (tg & 1) ? e1 : e0;
#pragma unroll
            for (int nt = 0; nt < 16; nt++) {
                uint32_t bf2[2];
                bf2[0] = __float_as_uint(Vp[(ks2 * 8 + tg) * PADV + nt * 8 + grp]);
                bf2[1] = __float_as_uint(Vp[(ks2 * 8 + tg + 4) * PADV + nt * 8 + grp]);
                mma_tf32(o[nt], af, bf2, o[nt]);
            }
        }
        __syncthreads();   // all warps done reading V(blk) and K(blk)

        // Issue next loads; ALWAYS commit 2 groups to keep wait arithmetic
        if (blk + 1 < nb) load_v(blk + 1);
        CP_COMMIT();
        if (blk + 2 < nb) load_k(blk + 2, (blk & 1) ? OFF_K1 : OFF_K0);
        CP_COMMIT();
    }

    // ---- epilogue (tf32-rounded for out-projection cp.async path) ----
    const float inv0 = 1.f / l0;
    const float inv1 = 1.f / l1;
    float* ob = O + (size_t)(b * SEQ + q0 + wid * 16) * HID + h * HD;
#pragma unroll
    for (int nt = 0; nt < 16; nt++) {
        int c = nt * 8 + 2 * tg;
        float v0 = __uint_as_float(cvt_tf32(o[nt][0] * inv0));
        float v1 = __uint_as_float(cvt_tf32(o[nt][1] * inv0));
        float v2 = __uint_as_float(cvt_tf32(o[nt][2] * inv1));
        float v3 = __uint_as_float(cvt_tf32(o[nt][3] * inv1));
        *(float2*)&ob[(size_t)grp * HID + c] = make_float2(v0, v1);
        *(float2*)&ob[(size_t)(grp + 8) * HID + c] = make_float2(v2, v3);
    }
}

// ===========================================================================
extern "C" void kernel_launch(void* const* d_in, const int* in_sizes, int n_in,
                              void* d_out, int out_size)
{
    const float* x  = (const float*)d_in[0];
    const float* wq = (const float*)d_in[1];
    const float* wk = (const float*)d_in[2];
    const float* wv = (const float*)d_in[3];
    const float* wo = (const float*)d_in[4];
    float* out = (float*)d_out;

    float *q, *k, *v, *o, *xr, *wqr, *wor;
    cudaGetSymbolAddress((void**)&q, g_q);
    cudaGetSymbolAddress((void**)&k, g_k);
    cudaGetSymbolAddress((void**)&v, g_v);
    cudaGetSymbolAddress((void**)&o, g_o);
    cudaGetSymbolAddress((void**)&xr, g_x);
    cudaGetSymbolAddress((void**)&wqr, g_wq);
    cudaGetSymbolAddress((void**)&wor, g_wo);

    cudaFuncSetAttribute(flash_mqa_tc,
                         cudaFuncAttributeMaxDynamicSharedMemorySize, FLASH_SMEM);
    cudaFuncSetAttribute(gemm_wide,
                         cudaFuncAttributeMaxDynamicSharedMemorySize, WSMEM);

    dim3 blk(256);

    // Round x, w_q, w_out to tf32
    round3_tf32<<<2048, 256>>>(x, xr, MROWS * HID / 4,
                               wq, wqr, HID * HID / 4,
                               wo, wor, HID * HID / 4);

    // Q projection (wide tensor GEMM, tf32-rounded output)
    gemm_wide<<<dim3(HID / 256, MROWS / 128), blk, WSMEM>>>(
        xr, wqr, q, MROWS, HID, HID, 1);

    // K and V projections fused (small GEMM)
    gemm_tf32<<<dim3(HD / 128, MROWS / 128, 2), blk>>>(
        x, wk, k, MROWS, HD, HID, 1, wv, v);

    // Tensor-core flash attention
    flash_mqa_tc<<<dim3(BATCH * NH, SEQ / BQ), blk, FLASH_SMEM>>>(q, k, v, o);

    // Output projection (wide tensor GEMM, full fp32 output)
    gemm_wide<<<dim3(HID / 256, MROWS / 128), blk, WSMEM>>>(
        o, wor, out, MROWS, HID, HID, 0);
}